// round 14
// baseline (speedup 1.0000x reference)
#include <cuda_runtime.h>
#include <stdint.h>

// MaskPyramids single-pass, SINGLE-WAVE persistent blocks.
// grid = (2, 512) = 1024 blocks (all resident at once on 148 SMs x 8 blocks),
// each block loops over half of its instance's 1024-float chunks (interleaved
// by chunk parity). Inner loop: warp-uniform window-row test (a warp's 128
// contiguous floats span <=2 grid rows; ~86% of chunks are pure zero stores)
// + 128B-line-aligned STG.128 (head h = (-start) mod 32 and tail <=3 elems
// handled scalar, verified R12/R13).
//
// Rounding replicates XLA's div->reciprocal-mul rewrite (verified exact R3):
//   rint( fl( fl(p * fl(1/200)) * H ) ), all f32 RN-even.

#define N_INST   512
#define G        28
#define CTRK     13
#define PER_INST 53294   // 40000 + 10000 + 2500 + 625 + 169

__device__ __forceinline__ float mval(const float* __restrict__ mask,
                                      int si, int sj) {
    return ((unsigned)si < (unsigned)G && (unsigned)sj < (unsigned)G)
               ? __ldg(&mask[si * G + sj]) : 0.0f;
}

template<int H>
__device__ __forceinline__ void do_level(int part, int c0, int b0, int h,
                                         const float* __restrict__ mask,
                                         float* __restrict__ outlevel) {
    constexpr int NELEM = H * H;
    const int NB   = (NELEM - h) >> 2;            // aligned-body f4 count
    const int NCH  = (NB + 255) >> 8;             // 256-f4 chunks
    const int tid  = threadIdx.x;
    const int lane0 = tid & ~31;

    for (int c = part; c < NCH; c += 2) {
        const int f4 = c * 256 + tid;
        if (f4 >= NB) break;

        // warp-uniform window-row intersection test
        const int S  = h + (c * 256 + lane0) * 4; // warp's first float offset
        const int rA = S / H;                     // compile-time magic div
        const int rB = (S + 127) / H;
        const bool warp_hit = (rB + c0 >= 0) && (rA + c0 <= G - 1);

        const int off = h + f4 * 4;
        if (!warp_hit) {
            *reinterpret_cast<float4*>(outlevel + off) =
                make_float4(0.f, 0.f, 0.f, 0.f);
        } else {
            const int row = off / H;
            const int col = off - row * H;
            const int si  = row + c0;
            float4 v = make_float4(0.f, 0.f, 0.f, 0.f);
            if (col <= H - 4) {                   // no row straddle
                const int sj = col - b0;
                if ((unsigned)si < (unsigned)G && sj > -4 && sj < G) {
                    const float* mrow = mask + si * G;
                    if ((unsigned)(sj + 0) < (unsigned)G) v.x = __ldg(&mrow[sj + 0]);
                    if ((unsigned)(sj + 1) < (unsigned)G) v.y = __ldg(&mrow[sj + 1]);
                    if ((unsigned)(sj + 2) < (unsigned)G) v.z = __ldg(&mrow[sj + 2]);
                    if ((unsigned)(sj + 3) < (unsigned)G) v.w = __ldg(&mrow[sj + 3]);
                }
            } else {                              // straddle (h%4!=0, rare)
                float ve[4];
                #pragma unroll
                for (int e = 0; e < 4; e++) {
                    int cc = col + e, r = si;
                    if (cc >= H) { cc -= H; r += 1; }
                    ve[e] = mval(mask, r, cc - b0);
                }
                v = make_float4(ve[0], ve[1], ve[2], ve[3]);
            }
            *reinterpret_cast<float4*>(outlevel + off) = v;
        }
    }

    if (part == 0) {
        // head: elements [0, h), all in row 0
        if (tid < h)
            outlevel[tid] = mval(mask, c0, tid - b0);
        // tail: t = (NELEM - h) & 3 elements at the very end, row H-1
        const int t = (NELEM - h) & 3;
        const int j = tid - 64;
        if (j >= 0 && j < t)
            outlevel[NELEM - t + j] = mval(mask, H - 1 + c0, H - t + j - b0);
    }
}

template<int H, int BASE, int N>
__device__ __forceinline__ void do_tail_level(int part, float pp0, float pp1,
                                              const float* __restrict__ mask,
                                              float* __restrict__ outrow) {
    const int lh = (int)rintf(__fmul_rn(pp0, (float)H));
    const int lw = (int)rintf(__fmul_rn(pp1, (float)H));
    const int c0 = CTRK - lh;
    const int b0 = lw - CTRK;
    for (int idx = part * 256 + threadIdx.x; idx < N; idx += 512) {
        const int row = idx / H;                  // compile-time magic div
        const int col = idx - row * H;
        outrow[BASE + idx] = mval(mask, row + c0, col - b0);
    }
}

__global__ void __launch_bounds__(256)
fused_kernel(const int* __restrict__ pos,
             const float* __restrict__ mask,
             float* __restrict__ out) {
    const int inst = blockIdx.y;
    const int part = blockIdx.x;                  // 0 or 1

    const float recip = 0.005f;  // fl(1/200) bit-exactly
    const float pp0 = __fmul_rn((float)__ldg(&pos[2 * inst + 0]), recip);
    const float pp1 = __fmul_rn((float)__ldg(&pos[2 * inst + 1]), recip);

    float* outrow = out + inst * PER_INST;
    // head length to first 128B line; level bases (0, 40000) are both
    // 0 mod 32 floats, so the same h applies to both big levels.
    const int h = (32 - ((inst * PER_INST) & 31)) & 31;

    {
        const int c0 = CTRK - (int)rintf(__fmul_rn(pp0, 200.f));
        const int b0 = (int)rintf(__fmul_rn(pp1, 200.f)) - CTRK;
        do_level<200>(part, c0, b0, h, mask, outrow);
    }
    {
        const int c0 = CTRK - (int)rintf(__fmul_rn(pp0, 100.f));
        const int b0 = (int)rintf(__fmul_rn(pp1, 100.f)) - CTRK;
        do_level<100>(part, c0, b0, h, mask, outrow + 40000);
    }
    do_tail_level<50, 50000, 2500>(part, pp0, pp1, mask, outrow);
    do_tail_level<25, 52500, 625>(part, pp0, pp1, mask, outrow);
    do_tail_level<13, 53125, 169>(part, pp0, pp1, mask, outrow);
}

extern "C" void kernel_launch(void* const* d_in, const int* in_sizes, int n_in,
                              void* d_out, int out_size) {
    const int*   pos  = (const int*)d_in[0];      // int32 [512, 2]
    const float* mask = (const float*)d_in[1];    // float32 [28, 28]
    float*       out  = (float*)d_out;            // float32 [512, 53294]

    fused_kernel<<<dim3(2, N_INST), 256>>>(pos, mask, out);
}

// round 15
// speedup vs baseline: 1.0845x; 1.0845x over previous
#include <cuda_runtime.h>
#include <stdint.h>

// MaskPyramids single-pass, single-launch, 256-BIT STORES (st.global.v8.f32,
// Blackwell) on 128B-line-aligned regions + warp-uniform window-row test.
//
// grid = (14, 512): bx 0-9 -> level 200x200, bx 10-12 -> level 100x100,
// bx 13 -> levels 50/25/13 (scalar tail levels). Each thread: 2 iterations of
// 8 floats (32B-aligned; h is even so h+8k is 32B-aligned). A warp covers 256
// contiguous floats (<=2 grid rows at H=200); if neither row intersects the
// 28-row window band (~86%), lanes store zero v8 with no per-lane math.
// Head h=(-start) mod 32 and tail (NELEM-h)&7 elems handled scalar (verified
// R12/R13 scheme).
//
// Rounding replicates XLA's div->reciprocal-mul rewrite (verified exact R3):
//   rint( fl( fl(p * fl(1/200)) * H ) ), all f32 RN-even.

#define N_INST   512
#define G        28
#define CTRK     13
#define PER_INST 53294   // 40000 + 10000 + 2500 + 625 + 169

__device__ __forceinline__ float mval(const float* __restrict__ mask,
                                      int si, int sj) {
    return ((unsigned)si < (unsigned)G && (unsigned)sj < (unsigned)G)
               ? __ldg(&mask[si * G + sj]) : 0.0f;
}

__device__ __forceinline__ void stg256(float* p, const float* v) {
    asm volatile("st.global.v8.f32 [%0], {%1,%2,%3,%4,%5,%6,%7,%8};"
                 :: "l"(p), "f"(v[0]), "f"(v[1]), "f"(v[2]), "f"(v[3]),
                    "f"(v[4]), "f"(v[5]), "f"(v[6]), "f"(v[7])
                 : "memory");
}

template<int H>
__device__ __forceinline__ void do_level(int chunk, int c0, int b0, int h,
                                         const float* __restrict__ mask,
                                         float* __restrict__ outlevel) {
    constexpr int NELEM = H * H;
    const int NB  = (NELEM - h) >> 3;          // aligned-body f8 count
    const int tid = threadIdx.x;
    const int lane0 = tid & ~31;

    #pragma unroll
    for (int k = 0; k < 2; k++) {
        const int f8 = chunk * 512 + k * 256 + tid;
        if (f8 >= NB) break;

        // warp-uniform window-row intersection test (256 floats per warp)
        const int S  = h + (chunk * 512 + k * 256 + lane0) * 8;
        const int rA = S / H;                  // compile-time magic div
        const int rB = (S + 255) / H;
        const bool warp_hit = (rB + c0 >= 0) && (rA + c0 <= G - 1);

        const int off = h + f8 * 8;
        float v[8];
        #pragma unroll
        for (int e = 0; e < 8; e++) v[e] = 0.0f;

        if (warp_hit) {
            const int row = off / H;
            const int col = off - row * H;
            const int si  = row + c0;
            if (col <= H - 8) {                // no row straddle (common)
                const int sj = col - b0;
                if ((unsigned)si < (unsigned)G && sj > -8 && sj < G) {
                    const float* mrow = mask + si * G;
                    #pragma unroll
                    for (int e = 0; e < 8; e++) {
                        const int s = sj + e;
                        if ((unsigned)s < (unsigned)G) v[e] = __ldg(&mrow[s]);
                    }
                }
            } else {                           // straddle (rare)
                #pragma unroll
                for (int e = 0; e < 8; e++) {
                    int cc = col + e, r = si;
                    if (cc >= H) { cc -= H; r += 1; }
                    v[e] = mval(mask, r, cc - b0);
                }
            }
        }
        stg256(outlevel + off, v);
    }

    if (chunk == 0) {
        // head: elements [0, h), all in row 0
        if (tid < h)
            outlevel[tid] = mval(mask, c0, tid - b0);
        // tail: t = (NELEM - h) & 7 elements at the very end, row H-1
        const int t = (NELEM - h) & 7;
        const int j = tid - 64;
        if (j >= 0 && j < t)
            outlevel[NELEM - t + j] = mval(mask, H - 1 + c0, H - t + j - b0);
    }
}

template<int H, int BASE, int N>
__device__ __forceinline__ void do_tail_level(float pp0, float pp1,
                                              const float* __restrict__ mask,
                                              float* __restrict__ outrow) {
    const int lh = (int)rintf(__fmul_rn(pp0, (float)H));
    const int lw = (int)rintf(__fmul_rn(pp1, (float)H));
    const int c0 = CTRK - lh;
    const int b0 = lw - CTRK;
    for (int idx = threadIdx.x; idx < N; idx += 256) {
        const int row = idx / H;               // compile-time magic div
        const int col = idx - row * H;
        outrow[BASE + idx] = mval(mask, row + c0, col - b0);
    }
}

__global__ void __launch_bounds__(256)
fused_kernel(const int* __restrict__ pos,
             const float* __restrict__ mask,
             float* __restrict__ out) {
    const int inst = blockIdx.y;
    const int bx   = blockIdx.x;

    const float recip = 0.005f;  // fl(1/200) bit-exactly
    const float pp0 = __fmul_rn((float)__ldg(&pos[2 * inst + 0]), recip);
    const float pp1 = __fmul_rn((float)__ldg(&pos[2 * inst + 1]), recip);

    float* outrow = out + inst * PER_INST;
    // head to first 128B line; level bases (0, 40000) both 0 mod 32 floats,
    // so the same h serves both big levels. h is even (53294 % 32 = 14).
    const int h = (32 - ((inst * PER_INST) & 31)) & 31;

    if (bx < 10) {
        const int c0 = CTRK - (int)rintf(__fmul_rn(pp0, 200.f));
        const int b0 = (int)rintf(__fmul_rn(pp1, 200.f)) - CTRK;
        do_level<200>(bx, c0, b0, h, mask, outrow);
    } else if (bx < 13) {
        const int c0 = CTRK - (int)rintf(__fmul_rn(pp0, 100.f));
        const int b0 = (int)rintf(__fmul_rn(pp1, 100.f)) - CTRK;
        do_level<100>(bx - 10, c0, b0, h, mask, outrow + 40000);
    } else {
        do_tail_level<50, 50000, 2500>(pp0, pp1, mask, outrow);
        do_tail_level<25, 52500, 625>(pp0, pp1, mask, outrow);
        do_tail_level<13, 53125, 169>(pp0, pp1, mask, outrow);
    }
}

extern "C" void kernel_launch(void* const* d_in, const int* in_sizes, int n_in,
                              void* d_out, int out_size) {
    const int*   pos  = (const int*)d_in[0];      // int32 [512, 2]
    const float* mask = (const float*)d_in[1];    // float32 [28, 28]
    float*       out  = (float*)d_out;            // float32 [512, 53294]

    fused_kernel<<<dim3(14, N_INST), 256>>>(pos, mask, out);
}

// round 16
// speedup vs baseline: 1.1096x; 1.0231x over previous
#include <cuda_runtime.h>
#include <stdint.h>

// MaskPyramids single-pass, single-launch. 256-bit stores (st.global.v8.f32)
// on 128B-line-aligned regions + BLOCK-uniform zero fast path: a block covers
// 4096 contiguous floats (~20.5 rows at H=200); if the block's row range
// misses the 28-row window band (~76% of big-level blocks), every thread runs
// a bare 2x v8-zero-store loop with no window math at all. Band-intersecting
// blocks run the warp-uniform + per-lane path (verified R13/R15).
//
// grid = (14, 512): bx 0-9 -> level 200x200, bx 10-12 -> level 100x100,
// bx 13 -> levels 50/25/13 (scalar tail levels). Head h = (-start) mod 32 and
// tail (NELEM-h)&7 elems handled scalar by chunk-0 spare threads (verified).
//
// Rounding replicates XLA's div->reciprocal-mul rewrite (verified exact R3):
//   rint( fl( fl(p * fl(1/200)) * H ) ), all f32 RN-even.

#define N_INST   512
#define G        28
#define CTRK     13
#define PER_INST 53294   // 40000 + 10000 + 2500 + 625 + 169

__device__ __forceinline__ float mval(const float* __restrict__ mask,
                                      int si, int sj) {
    return ((unsigned)si < (unsigned)G && (unsigned)sj < (unsigned)G)
               ? __ldg(&mask[si * G + sj]) : 0.0f;
}

__device__ __forceinline__ void stg256(float* p, const float* v) {
    asm volatile("st.global.v8.f32 [%0], {%1,%2,%3,%4,%5,%6,%7,%8};"
                 :: "l"(p), "f"(v[0]), "f"(v[1]), "f"(v[2]), "f"(v[3]),
                    "f"(v[4]), "f"(v[5]), "f"(v[6]), "f"(v[7])
                 : "memory");
}

__device__ __forceinline__ void stg256_zero(float* p) {
    float z[8] = {0.f, 0.f, 0.f, 0.f, 0.f, 0.f, 0.f, 0.f};
    stg256(p, z);
}

template<int H>
__device__ __forceinline__ void do_level(int chunk, int c0, int b0, int h,
                                         const float* __restrict__ mask,
                                         float* __restrict__ outlevel) {
    constexpr int NELEM = H * H;
    const int NB  = (NELEM - h) >> 3;          // aligned-body f8 count
    const int tid = threadIdx.x;

    // ---- block-uniform window-band test (block covers 4096 floats) ----
    const int S0  = h + chunk * 4096;          // block's first float offset
    const int S1  = S0 + 4095;
    const int rA0 = S0 / H;                    // compile-time magic div
    const int rB0 = S1 / H;
    const bool blk_hit = (rB0 + c0 >= 0) && (rA0 + c0 <= G - 1);

    if (!blk_hit) {
        // pure zero path: no window math at all
        #pragma unroll
        for (int k = 0; k < 2; k++) {
            const int f8 = chunk * 512 + k * 256 + tid;
            if (f8 < NB) stg256_zero(outlevel + h + f8 * 8);
        }
    } else {
        const int lane0 = tid & ~31;
        #pragma unroll
        for (int k = 0; k < 2; k++) {
            const int f8 = chunk * 512 + k * 256 + tid;
            if (f8 >= NB) break;

            // warp-uniform test (256 floats per warp)
            const int S  = h + (chunk * 512 + k * 256 + lane0) * 8;
            const int rA = S / H;
            const int rB = (S + 255) / H;
            const bool warp_hit = (rB + c0 >= 0) && (rA + c0 <= G - 1);

            const int off = h + f8 * 8;
            float v[8];
            #pragma unroll
            for (int e = 0; e < 8; e++) v[e] = 0.0f;

            if (warp_hit) {
                const int row = off / H;
                const int col = off - row * H;
                const int si  = row + c0;
                if (col <= H - 8) {            // no row straddle (common)
                    const int sj = col - b0;
                    if ((unsigned)si < (unsigned)G && sj > -8 && sj < G) {
                        const float* mrow = mask + si * G;
                        #pragma unroll
                        for (int e = 0; e < 8; e++) {
                            const int s = sj + e;
                            if ((unsigned)s < (unsigned)G) v[e] = __ldg(&mrow[s]);
                        }
                    }
                } else {                       // straddle (rare)
                    #pragma unroll
                    for (int e = 0; e < 8; e++) {
                        int cc = col + e, r = si;
                        if (cc >= H) { cc -= H; r += 1; }
                        v[e] = mval(mask, r, cc - b0);
                    }
                }
            }
            stg256(outlevel + off, v);
        }
    }

    if (chunk == 0) {
        // head: elements [0, h), all in row 0
        if (tid < h)
            outlevel[tid] = mval(mask, c0, tid - b0);
        // tail: t = (NELEM - h) & 7 elements at the very end, row H-1
        const int t = (NELEM - h) & 7;
        const int j = tid - 64;
        if (j >= 0 && j < t)
            outlevel[NELEM - t + j] = mval(mask, H - 1 + c0, H - t + j - b0);
    }
}

template<int H, int BASE, int N>
__device__ __forceinline__ void do_tail_level(float pp0, float pp1,
                                              const float* __restrict__ mask,
                                              float* __restrict__ outrow) {
    const int lh = (int)rintf(__fmul_rn(pp0, (float)H));
    const int lw = (int)rintf(__fmul_rn(pp1, (float)H));
    const int c0 = CTRK - lh;
    const int b0 = lw - CTRK;
    for (int idx = threadIdx.x; idx < N; idx += 256) {
        const int row = idx / H;               // compile-time magic div
        const int col = idx - row * H;
        outrow[BASE + idx] = mval(mask, row + c0, col - b0);
    }
}

__global__ void __launch_bounds__(256)
fused_kernel(const int* __restrict__ pos,
             const float* __restrict__ mask,
             float* __restrict__ out) {
    const int inst = blockIdx.y;
    const int bx   = blockIdx.x;

    const float recip = 0.005f;  // fl(1/200) bit-exactly
    const float pp0 = __fmul_rn((float)__ldg(&pos[2 * inst + 0]), recip);
    const float pp1 = __fmul_rn((float)__ldg(&pos[2 * inst + 1]), recip);

    float* outrow = out + inst * PER_INST;
    // head to first 128B line; level bases (0, 40000) both 0 mod 32 floats,
    // so the same h serves both big levels. h is even (53294 % 32 = 14).
    const int h = (32 - ((inst * PER_INST) & 31)) & 31;

    if (bx < 10) {
        const int c0 = CTRK - (int)rintf(__fmul_rn(pp0, 200.f));
        const int b0 = (int)rintf(__fmul_rn(pp1, 200.f)) - CTRK;
        do_level<200>(bx, c0, b0, h, mask, outrow);
    } else if (bx < 13) {
        const int c0 = CTRK - (int)rintf(__fmul_rn(pp0, 100.f));
        const int b0 = (int)rintf(__fmul_rn(pp1, 100.f)) - CTRK;
        do_level<100>(bx - 10, c0, b0, h, mask, outrow + 40000);
    } else {
        do_tail_level<50, 50000, 2500>(pp0, pp1, mask, outrow);
        do_tail_level<25, 52500, 625>(pp0, pp1, mask, outrow);
        do_tail_level<13, 53125, 169>(pp0, pp1, mask, outrow);
    }
}

extern "C" void kernel_launch(void* const* d_in, const int* in_sizes, int n_in,
                              void* d_out, int out_size) {
    const int*   pos  = (const int*)d_in[0];      // int32 [512, 2]
    const float* mask = (const float*)d_in[1];    // float32 [28, 28]
    float*       out  = (float*)d_out;            // float32 [512, 53294]

    fused_kernel<<<dim3(14, N_INST), 256>>>(pos, mask, out);
}